// round 5
// baseline (speedup 1.0000x reference)
#include <cuda_runtime.h>

// Inputs (metadata order):
//  0: link_pos_seq   [1024,32,8,3]    f32
//  1: link_rot_seq   [1024,32,8,3,3]  f32
//  2: sphere_centers [8,8,3]          f32
//  3: sphere_radii   [8,8]            f32
//  4: sdf_grid       [256,256,256]    f32
//  5: weight         scalar           f32
// Output: [1024,32] f32

#define GRID_N 256
#define N_LINKS 8
#define N_SPH 8
#define TB 256
#define HALF_ITEMS (1024 * 32 * 8 / 2)   // 131072

// Faithfully-rounded t/0.01 (mul + 2 fma Newton correction).
__device__ __forceinline__ float div001(float t) {
    const float q0 = t * 100.0f;
    return fmaf(fmaf(-0.01f, q0, t), 100.0f, q0);
}

__device__ __forceinline__ int vox(float t) {
    int i = (int)floorf(div001(t + 1.28f));
    return min(max(i, 0), GRID_N - 1);
}

__global__ __launch_bounds__(TB, 4)
void voxel_collision_kernel(const float* __restrict__ pos,
                            const float* __restrict__ rot,
                            const float* __restrict__ cen,
                            const float* __restrict__ rad,
                            const float* __restrict__ sdf,
                            const float* __restrict__ wptr,
                            float* __restrict__ out) {
    __shared__ float s_cen[N_LINKS * N_SPH * 3];   // 768 B
    __shared__ float s_rad[N_LINKS * N_SPH];       // 256 B

    const int tid = threadIdx.x;
    if (tid < N_LINKS * N_SPH * 3) s_cen[tid] = cen[tid];
    if (tid < N_LINKS * N_SPH)     s_rad[tid] = rad[tid];
    __syncthreads();

    const int gA = blockIdx.x * TB + tid;       // first item
    const int gB = gA + HALF_ITEMS;             // second item (same link id)
    const int l = gA & 7;

    // ---- issue ALL regular loads for both items up front (24 independent LDG) ----
    const float* RA = rot + (size_t)gA * 9;
    const float a00 = __ldg(RA + 0), a01 = __ldg(RA + 1), a02 = __ldg(RA + 2);
    const float a10 = __ldg(RA + 3), a11 = __ldg(RA + 4), a12 = __ldg(RA + 5);
    const float a20 = __ldg(RA + 6), a21 = __ldg(RA + 7), a22 = __ldg(RA + 8);
    const float* PA = pos + (size_t)gA * 3;
    const float pax = __ldg(PA + 0), pay = __ldg(PA + 1), paz = __ldg(PA + 2);

    const float* RB = rot + (size_t)gB * 9;
    const float b00 = __ldg(RB + 0), b01 = __ldg(RB + 1), b02 = __ldg(RB + 2);
    const float b10 = __ldg(RB + 3), b11 = __ldg(RB + 4), b12 = __ldg(RB + 5);
    const float b20 = __ldg(RB + 6), b21 = __ldg(RB + 7), b22 = __ldg(RB + 8);
    const float* PB = pos + (size_t)gB * 3;
    const float pbx = __ldg(PB + 0), pby = __ldg(PB + 1), pbz = __ldg(PB + 2);

    const float* lc = s_cen + l * (N_SPH * 3);
    const float* lr = s_rad + l * N_SPH;

    // ---- item A: addresses + issue gathers ----
    float vA[N_SPH];
    #pragma unroll
    for (int s = 0; s < N_SPH; s++) {
        const float cx = lc[s * 3 + 0], cy = lc[s * 3 + 1], cz = lc[s * 3 + 2];
        const float x = fmaf(a00, cx, fmaf(a01, cy, fmaf(a02, cz, pax)));
        const float y = fmaf(a10, cx, fmaf(a11, cy, fmaf(a12, cz, pay)));
        const float z = fmaf(a20, cx, fmaf(a21, cy, fmaf(a22, cz, paz)));
        vA[s] = __ldg(sdf + ((vox(x) << 16) | (vox(y) << 8) | vox(z)));
    }

    // ---- item B: addresses + issue gathers (overlaps A's in-flight gathers) ----
    float vB[N_SPH];
    #pragma unroll
    for (int s = 0; s < N_SPH; s++) {
        const float cx = lc[s * 3 + 0], cy = lc[s * 3 + 1], cz = lc[s * 3 + 2];
        const float x = fmaf(b00, cx, fmaf(b01, cy, fmaf(b02, cz, pbx)));
        const float y = fmaf(b10, cx, fmaf(b11, cy, fmaf(b12, cz, pby)));
        const float z = fmaf(b20, cx, fmaf(b21, cy, fmaf(b22, cz, pbz)));
        vB[s] = __ldg(sdf + ((vox(x) << 16) | (vox(y) << 8) | vox(z)));
    }

    // ---- consume A ----
    float mA = -3.402823466e+38f, mB = -3.402823466e+38f;
    #pragma unroll
    for (int s = 0; s < N_SPH; s++) {
        mA = fmaxf(mA, lr[s] - vA[s]);
        mB = fmaxf(mB, lr[s] - vB[s]);
    }

    float resA = fminf(fmaxf(mA - 0.01f, 0.0f), 0.5f) * 4.0f;
    float resB = fminf(fmaxf(mB - 0.01f, 0.0f), 0.5f) * 4.0f;

    resA += __shfl_xor_sync(0xffffffffu, resA, 1);
    resA += __shfl_xor_sync(0xffffffffu, resA, 2);
    resA += __shfl_xor_sync(0xffffffffu, resA, 4);
    resB += __shfl_xor_sync(0xffffffffu, resB, 1);
    resB += __shfl_xor_sync(0xffffffffu, resB, 2);
    resB += __shfl_xor_sync(0xffffffffu, resB, 4);

    if (l == 0) {
        const float w = __ldg(wptr);
        out[gA >> 3] = w * resA;
        out[gB >> 3] = w * resB;
    }
}

extern "C" void kernel_launch(void* const* d_in, const int* in_sizes, int n_in,
                              void* d_out, int out_size) {
    const float* pos = (const float*)d_in[0];
    const float* rot = (const float*)d_in[1];
    const float* cen = (const float*)d_in[2];
    const float* rad = (const float*)d_in[3];
    const float* sdf = (const float*)d_in[4];
    const float* w   = (const float*)d_in[5];
    float* out = (float*)d_out;

    // 262144 items, 2 per thread -> 512 blocks of 256
    voxel_collision_kernel<<<512, TB>>>(pos, rot, cen, rad, sdf, w, out);
}